// round 9
// baseline (speedup 1.0000x reference)
#include <cuda_runtime.h>

#define N_NODES 4096
#define D_DIM   2048
#define B_SAMP  64
#define BLK     512          // one float4 per thread per row (D/4 = 512)

#define A_T_C    0.3f
#define DSBETA_C 1e-4f
#define E_B_C    0.5f
#define E_N_C    0.005f      // 0.01 * E_B
#define EPS_DS_C 0.01f

// Persistent scratch (allocation-free).
__device__ float g_M[(size_t)N_NODES * D_DIM];
__device__ float g_ACT[(size_t)B_SAMP * N_NODES];   // [t][n] activations
__device__ unsigned long long g_best[B_SAMP];
__device__ unsigned int g_cnt[B_SAMP];
__device__ int g_nb_word32;  // 1 => neighbors stored as 32-bit words, 0 => bytes

__global__ void detect_kernel(const unsigned int* __restrict__ nb) {
    if (threadIdx.x < B_SAMP) g_cnt[threadIdx.x] = 0u;
    if (threadIdx.x == 0) {
        // Bool widened to int32 -> words are 0/1; to float32 -> 0/0x3F800000.
        // Raw byte-bools give random packed words; P(all 256 pass) ~ (1/8)^256.
        int w32 = 1;
        for (int i = 0; i < 256; i++) {
            unsigned v = nb[i];
            if (!(v == 0u || v == 1u || v == 0x3F800000u)) { w32 = 0; break; }
        }
        g_nb_word32 = w32;
    }
}

// Block-wide argmax of ACT column `slot` (BLK threads). Packed key:
// act bits (act>0 so float bit order is monotone) << 32 | (0xFFFFFFFF - n),
// so ties pick the SMALLEST node index (jnp.argmax first-occurrence).
__device__ __forceinline__ void column_argmax(int slot) {
    const int tid = threadIdx.x;
    const float* col = g_ACT + (size_t)slot * N_NODES;
    unsigned long long best = 0ULL;
#pragma unroll
    for (int k = 0; k < N_NODES / BLK; k++) {
        int i = k * BLK + tid;
        unsigned long long key =
            ((unsigned long long)__float_as_uint(col[i]) << 32) |
            (unsigned long long)(0xFFFFFFFFu - (unsigned)i);
        best = best > key ? best : key;
    }
#pragma unroll
    for (int o = 16; o > 0; o >>= 1) {
        unsigned long long other = __shfl_down_sync(0xffffffffu, best, o);
        best = best > other ? best : other;
    }
    __shared__ unsigned long long sk[BLK / 32];
    if ((tid & 31) == 0) sk[tid >> 5] = best;
    __syncthreads();
    if (tid == 0) {
#pragma unroll
        for (int i = 1; i < BLK / 32; i++) best = best > sk[i] ? best : sk[i];
        g_best[slot] = best;
    }
}

__global__ __launch_bounds__(BLK) void argmax0_kernel() { column_argmax(0); }

// Compute ACT[t][n] for all t from initial R, W. One block per node.
__global__ __launch_bounds__(BLK) void init_act_kernel(const float* __restrict__ X,
                                                       const float* __restrict__ Win,
                                                       const float* __restrict__ Rin) {
    const int n = blockIdx.x, tid = threadIdx.x;
    const int wrp = tid >> 5, lane = tid & 31;
    __shared__ float sred[64];
    __shared__ float s_rsum;

    float4 w = __ldg(((const float4*)(Win + (size_t)n * D_DIM)) + tid);
    float4 r = __ldg(((const float4*)(Rin + (size_t)n * D_DIM)) + tid);

    // rsum = sum(R row)
    float rs = r.x + r.y + r.z + r.w;
#pragma unroll
    for (int o = 16; o > 0; o >>= 1) rs += __shfl_down_sync(0xffffffffu, rs, o);
    if (lane == 0) sred[wrp] = rs;
    __syncthreads();
    if (tid == 0) {
        float s = 0.f;
#pragma unroll
        for (int i = 0; i < 16; i++) s += sred[i];
        s_rsum = s;
    }
    __syncthreads();
    const float rsum = s_rsum;

    for (int t0 = 0; t0 < B_SAMP; t0 += 4) {
        float dd[4];
#pragma unroll
        for (int g = 0; g < 4; g++) {
            float4 xv = __ldg(((const float4*)(X + (size_t)(t0 + g) * D_DIM)) + tid);
            float d0 = xv.x - w.x, d1 = xv.y - w.y, d2 = xv.z - w.z, d3 = xv.w - w.w;
            dd[g] = r.x * d0 * d0 + r.y * d1 * d1 + r.z * d2 * d2 + r.w * d3 * d3;
        }
#pragma unroll
        for (int o = 16; o > 0; o >>= 1) {
#pragma unroll
            for (int g = 0; g < 4; g++)
                dd[g] += __shfl_down_sync(0xffffffffu, dd[g], o);
        }
        if (lane == 0) {
#pragma unroll
            for (int g = 0; g < 4; g++) sred[wrp * 4 + g] = dd[g];
        }
        __syncthreads();
        if (tid < 4) {
            float s = 0.f;
#pragma unroll
            for (int i = 0; i < 16; i++) s += sred[i * 4 + tid];
            g_ACT[(size_t)(t0 + tid) * N_NODES + n] = rsum / (rsum + s + 1e-7f);
        }
        __syncthreads();
    }
}

// Step t: update winner+neighbor rows (W, M; R lives only in registers),
// recompute their ACT entries for future samples, then the LAST block of the
// grid computes the argmax of column t+1 (fused; no extra launch).
__global__ __launch_bounds__(BLK) void update_kernel(const float* __restrict__ X,
                                                     float* __restrict__ W,
                                                     const void* __restrict__ nbv,
                                                     int t) {
    const int n = blockIdx.x, tid = threadIdx.x;
    const int wrp = tid >> 5, lane = tid & 31;
    __shared__ float sred[64];
    __shared__ float s_av, s_den, s_rsum;
    __shared__ unsigned s_old;

    const unsigned long long key0 = g_best[t];
    const float pact = __uint_as_float((unsigned)(key0 >> 32));
    float lr = 0.f;
    if (pact >= A_T_C) {   // else do_upd == false -> whole step is a no-op
        const int winner = (int)(0xFFFFFFFFu - (unsigned)(key0 & 0xFFFFFFFFu));
        if (n == winner) {
            lr = E_B_C;
        } else {
            const size_t idx = (size_t)winner * N_NODES + n;
            bool isnb = g_nb_word32 ? (((const unsigned int*)nbv)[idx] != 0u)
                                    : (((const unsigned char*)nbv)[idx] != 0);
            if (isnb) lr = E_N_C;
        }
    }

    if (lr > 0.f) {   // block-uniform predicate (depends only on blockIdx.x)
        float4* Wr = (float4*)(W   + (size_t)n * D_DIM);
        float4* Mr = (float4*)(g_M + (size_t)n * D_DIM);
        const float c = lr * DSBETA_C, omc = 1.0f - c;

        float4 wo = Wr[tid];
        float4 m  = Mr[tid];
        float4 xv = __ldg(((const float4*)(X + (size_t)t * D_DIM)) + tid);
        float d0 = xv.x - wo.x, d1 = xv.y - wo.y, d2 = xv.z - wo.z, d3 = xv.w - wo.w;
        float4 mn;
        mn.x = c * fabsf(d0) + omc * m.x;
        mn.y = c * fabsf(d1) + omc * m.y;
        mn.z = c * fabsf(d2) + omc * m.z;
        mn.w = c * fabsf(d3) + omc * m.w;
        float4 wn;
        wn.x = wo.x + lr * d0;
        wn.y = wo.y + lr * d1;
        wn.z = wo.z + lr * d2;
        wn.w = wo.w + lr * d3;

        // 3-way reduce over M_new: max, min, sum
        float pmax = fmaxf(fmaxf(mn.x, mn.y), fmaxf(mn.z, mn.w));
        float pmin = fminf(fminf(mn.x, mn.y), fminf(mn.z, mn.w));
        float psum = mn.x + mn.y + mn.z + mn.w;
#pragma unroll
        for (int o = 16; o > 0; o >>= 1) {
            pmax = fmaxf(pmax, __shfl_down_sync(0xffffffffu, pmax, o));
            pmin = fminf(pmin, __shfl_down_sync(0xffffffffu, pmin, o));
            psum +=            __shfl_down_sync(0xffffffffu, psum, o);
        }
        if (lane == 0) { sred[wrp] = pmax; sred[16 + wrp] = pmin; sred[32 + wrp] = psum; }
        __syncthreads();
        if (tid == 0) {
            float mx = -1e30f, mnv = 1e30f, sum = 0.f;
#pragma unroll
            for (int i = 0; i < 16; i++) {
                mx  = fmaxf(mx, sred[i]);
                mnv = fminf(mnv, sred[16 + i]);
                sum += sred[32 + i];
            }
            s_av  = sum / (float)D_DIM;
            s_den = EPS_DS_C * (mx - mnv);
        }
        __syncthreads();
        const float av = s_av, den = s_den;

        float4 r;
        if (den == 0.0f) {
            r.x = r.y = r.z = r.w = 1.0f;   // reference's NaN -> 1 path
        } else {
            float a0 = fminf(fmaxf((mn.x - av) / den, -80.0f), 80.0f);
            float a1 = fminf(fmaxf((mn.y - av) / den, -80.0f), 80.0f);
            float a2 = fminf(fmaxf((mn.z - av) / den, -80.0f), 80.0f);
            float a3 = fminf(fmaxf((mn.w - av) / den, -80.0f), 80.0f);
            r.x = 1.0f / (1.0f + expf(a0));
            r.y = 1.0f / (1.0f + expf(a1));
            r.z = 1.0f / (1.0f + expf(a2));
            r.w = 1.0f / (1.0f + expf(a3));
        }
        Wr[tid] = wn;
        Mr[tid] = mn;

        // rsum of R_new
        float rs = r.x + r.y + r.z + r.w;
#pragma unroll
        for (int o = 16; o > 0; o >>= 1) rs += __shfl_down_sync(0xffffffffu, rs, o);
        __syncthreads();
        if (lane == 0) sred[wrp] = rs;
        __syncthreads();
        if (tid == 0) {
            float s = 0.f;
#pragma unroll
            for (int i = 0; i < 16; i++) s += sred[i];
            s_rsum = s;
        }
        __syncthreads();
        const float rsum = s_rsum;

        // Recompute this row's activations for all future samples.
        for (int t0 = t + 1; t0 < B_SAMP; t0 += 4) {
            const int cnt = (B_SAMP - t0 < 4) ? (B_SAMP - t0) : 4;
            float dd[4];
#pragma unroll
            for (int g = 0; g < 4; g++) {
                if (g < cnt) {
                    float4 xa = __ldg(((const float4*)(X + (size_t)(t0 + g) * D_DIM)) + tid);
                    float e0 = xa.x - wn.x, e1 = xa.y - wn.y,
                          e2 = xa.z - wn.z, e3 = xa.w - wn.w;
                    dd[g] = r.x * e0 * e0 + r.y * e1 * e1 + r.z * e2 * e2 + r.w * e3 * e3;
                } else dd[g] = 0.f;
            }
#pragma unroll
            for (int o = 16; o > 0; o >>= 1) {
#pragma unroll
                for (int g = 0; g < 4; g++)
                    dd[g] += __shfl_down_sync(0xffffffffu, dd[g], o);
            }
            if (lane == 0) {
#pragma unroll
                for (int g = 0; g < 4; g++) sred[wrp * 4 + g] = dd[g];
            }
            __syncthreads();
            if (tid < cnt) {
                float s = 0.f;
#pragma unroll
                for (int i = 0; i < 16; i++) s += sred[i * 4 + tid];
                g_ACT[(size_t)(t0 + tid) * N_NODES + n] = rsum / (rsum + s + 1e-7f);
            }
            __syncthreads();
        }
    }

    // Epilogue: every block counts in; the LAST one computes next argmax.
    if (t + 1 < B_SAMP) {
        __threadfence();
        if (tid == 0) s_old = atomicAdd(&g_cnt[t], 1u);
        __syncthreads();
        if (s_old == (unsigned)(N_NODES - 1)) {
            __threadfence();
            column_argmax(t + 1);
        }
    }
}

extern "C" void kernel_launch(void* const* d_in, const int* in_sizes, int n_in,
                              void* d_out, int out_size) {
    const float* x          = (const float*)d_in[0];   // [B, D]
    const float* weights    = (const float*)d_in[1];   // [N, D]
    const float* moving_avg = (const float*)d_in[2];   // [N, D]
    const float* relevances = (const float*)d_in[3];   // [N, D]
    // d_in[4] = wins (unused for output)
    const void*  neighbors  = d_in[5];                 // [N, N] bool (width auto-detected)

    float* W = (float*)d_out;

    void* pM = nullptr;
    cudaGetSymbolAddress(&pM, g_M);

    const size_t bytes = sizeof(float) * (size_t)N_NODES * D_DIM;
    cudaMemcpyAsync(W,  weights,    bytes, cudaMemcpyDeviceToDevice);
    cudaMemcpyAsync(pM, moving_avg, bytes, cudaMemcpyDeviceToDevice);

    detect_kernel<<<1, 64>>>((const unsigned int*)neighbors);
    init_act_kernel<<<N_NODES, BLK>>>(x, weights, relevances);
    argmax0_kernel<<<1, BLK>>>();

    for (int t = 0; t < B_SAMP; t++) {
        update_kernel<<<N_NODES, BLK>>>(x, W, neighbors, t);
    }
}

// round 10
// speedup vs baseline: 3.5000x; 3.5000x over previous
#include <cuda_runtime.h>

#define N_NODES 4096
#define D_DIM   2048
#define B_SAMP  64

#define A_T_C    0.3f
#define DSBETA_C 1e-4f
#define E_B_C    0.5f
#define E_N_C    0.005f      // 0.01 * E_B
#define EPS_DS_C 0.01f

// Persistent state across the sequential scan (allocation-free scratch).
__device__ float g_M[(size_t)N_NODES * D_DIM];
__device__ float g_R[(size_t)N_NODES * D_DIM];
__device__ unsigned long long g_best[B_SAMP];
__device__ int g_nb_word32;   // 1 => neighbors stored as 32-bit words, 0 => bytes

__global__ void reset_best_kernel(const unsigned int* __restrict__ nb) {
    if (threadIdx.x < B_SAMP) g_best[threadIdx.x] = 0ULL;
    if (threadIdx.x == 0) {
        // Bool widened to int32 -> words are 0/1; to float32 -> 0/0x3F800000.
        // Raw byte-bools give random packed words; P(all 256 pass) ~ (1/8)^256.
        int w32 = 1;
        for (int i = 0; i < 256; i++) {
            unsigned v = nb[i];
            if (!(v == 0u || v == 1u || v == 0x3F800000u)) { w32 = 0; break; }
        }
        g_nb_word32 = w32;
    }
}

// Phase A: per-node activation + packed argmax via atomicMax.
// One block per node; 256 threads stream the D=2048 row as float4.
// W and R reads use DEFAULT cache policy: they are the arrays we want
// resident in L2 across steps.
__global__ __launch_bounds__(256) void act_kernel(const float* __restrict__ x,
                                                  const float* __restrict__ W,
                                                  int t) {
    const int n   = blockIdx.x;
    const int tid = threadIdx.x;
    const float4* Wr = (const float4*)(W   + (size_t)n * D_DIM);
    const float4* Rr = (const float4*)(g_R + (size_t)n * D_DIM);
    const float4* xr = (const float4*)x;

    float dist = 0.f, rsum = 0.f;
#pragma unroll
    for (int k = 0; k < (D_DIM / 4) / 256; k++) {
        int i = k * 256 + tid;
        float4 w  = Wr[i];
        float4 r  = Rr[i];
        float4 xv = __ldg(&xr[i]);
        float d0 = xv.x - w.x, d1 = xv.y - w.y, d2 = xv.z - w.z, d3 = xv.w - w.w;
        dist += r.x * d0 * d0 + r.y * d1 * d1 + r.z * d2 * d2 + r.w * d3 * d3;
        rsum += r.x + r.y + r.z + r.w;
    }
#pragma unroll
    for (int o = 16; o > 0; o >>= 1) {
        dist += __shfl_down_sync(0xffffffffu, dist, o);
        rsum += __shfl_down_sync(0xffffffffu, rsum, o);
    }
    __shared__ float sd[8], sr[8];
    int wrp = tid >> 5, lane = tid & 31;
    if (lane == 0) { sd[wrp] = dist; sr[wrp] = rsum; }
    __syncthreads();
    if (tid == 0) {
        float dt = 0.f, rt = 0.f;
#pragma unroll
        for (int i = 0; i < 8; i++) { dt += sd[i]; rt += sr[i]; }
        float act = rt / (rt + dt + 1e-7f);
        // act > 0 always (R > 0) so the float bit pattern is order-preserving.
        // Low word = 0xFFFFFFFF - n: ties pick the SMALLEST node index
        // (matches jnp.argmax first-occurrence semantics).
        unsigned long long key =
            ((unsigned long long)__float_as_uint(act) << 32) |
            (unsigned long long)(0xFFFFFFFFu - (unsigned)n);
        unsigned long long cur = g_best[t];
        if (key > cur) atomicMax(&g_best[t], key);
    }
}

// Phase B: update winner + neighbors. One block per node; inactive blocks
// early-exit after one neighbor read. M is touched ONLY here and never read
// by act, so it streams through L2 with evict-first hints (__ldcs/__stcs)
// to protect W/R residency.
__global__ __launch_bounds__(256) void update_kernel(const float* __restrict__ x,
                                                     float* __restrict__ W,
                                                     const void* __restrict__ nbv,
                                                     int t) {
    const unsigned long long key = g_best[t];
    const float act = __uint_as_float((unsigned)(key >> 32));
    if (!(act >= A_T_C)) return;  // do_upd == false -> whole step is a no-op
    const int winner = (int)(0xFFFFFFFFu - (unsigned)(key & 0xFFFFFFFFu));

    const int n = blockIdx.x;
    float lr;
    if (n == winner) {
        lr = E_B_C;
    } else {
        bool isnb;
        const size_t idx = (size_t)winner * N_NODES + n;
        if (g_nb_word32) {
            isnb = __ldcs((const unsigned int*)nbv + idx) != 0u;
        } else {
            isnb = __ldcs((const unsigned char*)nbv + idx) != 0;
        }
        if (!isnb) return;
        lr = E_N_C;
    }

    const int tid = threadIdx.x;
    float4* Wr = (float4*)(W   + (size_t)n * D_DIM);
    float4* Mr = (float4*)(g_M + (size_t)n * D_DIM);
    float4* Rr = (float4*)(g_R + (size_t)n * D_DIM);
    const float4* xr = (const float4*)x;

    const float c   = lr * DSBETA_C;
    const float omc = 1.0f - c;

    float4 Mn[2], Wn[2];
    float pmax = -1e30f, pmin = 1e30f, psum = 0.f;
#pragma unroll
    for (int k = 0; k < 2; k++) {
        int i = k * 256 + tid;
        float4 w  = Wr[i];
        float4 m  = __ldcs(Mr + i);               // M: evict-first
        float4 xv = __ldg(&xr[i]);
        float d0 = xv.x - w.x, d1 = xv.y - w.y, d2 = xv.z - w.z, d3 = xv.w - w.w;
        float4 mn;
        mn.x = c * fabsf(d0) + omc * m.x;
        mn.y = c * fabsf(d1) + omc * m.y;
        mn.z = c * fabsf(d2) + omc * m.z;
        mn.w = c * fabsf(d3) + omc * m.w;
        Mn[k] = mn;
        float4 wn;
        wn.x = w.x + lr * d0;
        wn.y = w.y + lr * d1;
        wn.z = w.z + lr * d2;
        wn.w = w.w + lr * d3;
        Wn[k] = wn;
        pmax = fmaxf(pmax, fmaxf(fmaxf(mn.x, mn.y), fmaxf(mn.z, mn.w)));
        pmin = fminf(pmin, fminf(fminf(mn.x, mn.y), fminf(mn.z, mn.w)));
        psum += mn.x + mn.y + mn.z + mn.w;
    }
    // 3-way block reduction (max, min, sum of M_new over the row)
#pragma unroll
    for (int o = 16; o > 0; o >>= 1) {
        pmax = fmaxf(pmax, __shfl_down_sync(0xffffffffu, pmax, o));
        pmin = fminf(pmin, __shfl_down_sync(0xffffffffu, pmin, o));
        psum +=            __shfl_down_sync(0xffffffffu, psum, o);
    }
    __shared__ float smax[8], smin[8], ssum[8];
    __shared__ float s_av, s_den;
    int wrp = tid >> 5, lane = tid & 31;
    if (lane == 0) { smax[wrp] = pmax; smin[wrp] = pmin; ssum[wrp] = psum; }
    __syncthreads();
    if (tid == 0) {
        float mx = -1e30f, mnv = 1e30f, sum = 0.f;
#pragma unroll
        for (int i = 0; i < 8; i++) {
            mx  = fmaxf(mx, smax[i]);
            mnv = fminf(mnv, smin[i]);
            sum += ssum[i];
        }
        s_av  = sum / (float)D_DIM;
        s_den = EPS_DS_C * (mx - mnv);
    }
    __syncthreads();
    const float av  = s_av;
    const float den = s_den;
    const bool  zero = (den == 0.0f);

#pragma unroll
    for (int k = 0; k < 2; k++) {
        int i = k * 256 + tid;
        float4 mn = Mn[k];
        float4 r;
        if (zero) {
            r.x = r.y = r.z = r.w = 1.0f;   // matches reference's NaN->1 path
        } else {
            float a0 = fminf(fmaxf((mn.x - av) / den, -80.0f), 80.0f);
            float a1 = fminf(fmaxf((mn.y - av) / den, -80.0f), 80.0f);
            float a2 = fminf(fmaxf((mn.z - av) / den, -80.0f), 80.0f);
            float a3 = fminf(fmaxf((mn.w - av) / den, -80.0f), 80.0f);
            r.x = 1.0f / (1.0f + expf(a0));
            r.y = 1.0f / (1.0f + expf(a1));
            r.z = 1.0f / (1.0f + expf(a2));
            r.w = 1.0f / (1.0f + expf(a3));
        }
        __stcs(Mr + i, mn);                       // M: evict-first
        Rr[i] = r;                                // R/W: keep L2-resident
        Wr[i] = Wn[k];
    }
}

extern "C" void kernel_launch(void* const* d_in, const int* in_sizes, int n_in,
                              void* d_out, int out_size) {
    const float* x          = (const float*)d_in[0];   // [B, D]
    const float* weights    = (const float*)d_in[1];   // [N, D]
    const float* moving_avg = (const float*)d_in[2];   // [N, D]
    const float* relevances = (const float*)d_in[3];   // [N, D]
    // d_in[4] = wins (unused for output)
    const void*  neighbors  = d_in[5];                 // [N, N] bool (width auto-detected)

    float* W = (float*)d_out;

    void *pM = nullptr, *pR = nullptr;
    cudaGetSymbolAddress(&pM, g_M);
    cudaGetSymbolAddress(&pR, g_R);

    const size_t bytes = sizeof(float) * (size_t)N_NODES * D_DIM;
    cudaMemcpyAsync(W,  weights,    bytes, cudaMemcpyDeviceToDevice);
    cudaMemcpyAsync(pM, moving_avg, bytes, cudaMemcpyDeviceToDevice);
    cudaMemcpyAsync(pR, relevances, bytes, cudaMemcpyDeviceToDevice);

    reset_best_kernel<<<1, 64>>>((const unsigned int*)neighbors);

    for (int t = 0; t < B_SAMP; t++) {
        const float* xt = x + (size_t)t * D_DIM;
        act_kernel<<<N_NODES, 256>>>(xt, W, t);
        update_kernel<<<N_NODES, 256>>>(xt, W, neighbors, t);
    }
}